// round 4
// baseline (speedup 1.0000x reference)
#include <cuda_runtime.h>
#include <cuda_bf16.h>
#include <cstdint>

#define NN 50000
#define NE 800000
#define BSTRIDE 64   // per-dst bucket capacity; P(deg>=64)~1e-13 for Poisson(16)

// Scratch (allocation-free rule: __device__ globals)
__device__ __align__(16) float g_z[NN][256];   // z: [node][gate*128 + h*64 + f]
__device__ float4 g_attl[NN];                  // el dots {g0h0,g0h1,g1h0,g1h1}
__device__ float4 g_attr[NN];                  // er dots
__device__ int    g_deg[NN];                   // incoming-degree cursor
__device__ int    g_bsrc[NN * BSTRIDE];        // bucket: src node per slot
__device__ float4 g_bex[NN * BSTRIDE];         // bucket: exp(e) per slot
// Pre-converted weights, [k][n'] with n' = gate*128 + col (bf16 hi/lo split)
__device__ __align__(16) __nv_bfloat16 g_Wh[128 * 256];
__device__ __align__(16) __nv_bfloat16 g_Wl[128 * 256];

// ============================ mma helpers ==================================
__device__ __forceinline__ void ldsm4(uint32_t* r, uint32_t addr) {
  asm volatile("ldmatrix.sync.aligned.m8n8.x4.shared.b16 {%0,%1,%2,%3}, [%4];"
               : "=r"(r[0]), "=r"(r[1]), "=r"(r[2]), "=r"(r[3]) : "r"(addr));
}
__device__ __forceinline__ void ldsm4t(uint32_t* r, uint32_t addr) {
  asm volatile("ldmatrix.sync.aligned.m8n8.x4.trans.shared.b16 {%0,%1,%2,%3}, [%4];"
               : "=r"(r[0]), "=r"(r[1]), "=r"(r[2]), "=r"(r[3]) : "r"(addr));
}
__device__ __forceinline__ void mma_bf16(float* d, const uint32_t* a,
                                         const uint32_t* b) {
  asm volatile(
      "mma.sync.aligned.m16n8k16.row.col.f32.bf16.bf16.f32 "
      "{%0,%1,%2,%3}, {%4,%5,%6,%7}, {%8,%9}, {%0,%1,%2,%3};"
      : "+f"(d[0]), "+f"(d[1]), "+f"(d[2]), "+f"(d[3])
      : "r"(a[0]), "r"(a[1]), "r"(a[2]), "r"(a[3]), "r"(b[0]), "r"(b[1]));
}

// bf16 hi/lo split of 2 floats, packed into 2x uint32 (bf16x2)
__device__ __forceinline__ void split2(float a, float b, uint32_t& hi, uint32_t& lo) {
  __nv_bfloat16 ha = __float2bfloat16(a), hb = __float2bfloat16(b);
  float ra = a - __bfloat162float(ha), rb = b - __bfloat162float(hb);
  __nv_bfloat16 la = __float2bfloat16(ra), lb = __float2bfloat16(rb);
  hi = (uint32_t)__bfloat16_as_ushort(ha) | ((uint32_t)__bfloat16_as_ushort(hb) << 16);
  lo = (uint32_t)__bfloat16_as_ushort(la) | ((uint32_t)__bfloat16_as_ushort(lb) << 16);
}

// ---------------------------------------------------------------------------
__global__ __launch_bounds__(256) void k_init() {
  int idx = blockIdx.x * blockDim.x + threadIdx.x;
  if (idx < NN) g_deg[idx] = 0;
}

// One-time weight conversion: W[(128+n')*128+k] -> g_Wh/g_Wl[k*256+n']
__global__ __launch_bounds__(256) void k_prep(const float* __restrict__ W) {
  int idx = blockIdx.x * blockDim.x + threadIdx.x;
  if (idx >= 128 * 256) return;
  int n = idx & 255, k = idx >> 8;
  float v = W[(size_t)(128 + n) * 128 + k];
  __nv_bfloat16 h = __float2bfloat16(v);
  __nv_bfloat16 l = __float2bfloat16(v - __bfloat162float(h));
  g_Wh[k * 256 + n] = h;
  g_Wl[k * 256 + n] = l;
}

// ============================ mma.sync GEMM ================================
// z[n][g*128+c] = sum_k x[n][k] * W[(1+g)*128+c][k]   (bf16 split, 3 products)
// CTA: 128 nodes x 128 cols (one gate), K=128 fully staged.
// A smem: [m][k] bf16, pitch 272B.  B smem: [k][n] bf16, pitch 272B.
#define APITCH 272
#define SA_HI  0
#define SA_LO  34816
#define SB_HI  69632
#define SB_LO  104448
#define SM_ATL 139264
#define SM_ATR 139776
#define SM_EL  140288
#define SM_ER  141312
#define SM_TOT 142336

__global__ __launch_bounds__(256, 1) void k_gemm_mma(const float* __restrict__ X,
                                                     const float* __restrict__ AL,
                                                     const float* __restrict__ AR) {
  extern __shared__ char sm[];
  const int tid = threadIdx.x;
  const int gate = blockIdx.x;         // 0=u, 1=c (orig idx 1,2)
  const int m0 = blockIdx.y * 128;

  // attention weights to smem
  if (tid < 128) {
    ((float*)(sm + SM_ATL))[tid] = AL[128 + gate * 128 + tid];
    ((float*)(sm + SM_ATR))[tid] = AR[128 + gate * 128 + tid];
  }

  // Stage A: X tile 128x128 f32 -> bf16 hi/lo, [m][k]
  for (int it = tid; it < 128 * 32; it += 256) {
    int row = it >> 5, k4 = it & 31;
    int node = m0 + row;
    float4 v = make_float4(0.f, 0.f, 0.f, 0.f);
    if (node < NN) v = *(const float4*)(X + (size_t)node * 128 + k4 * 4);
    uint32_t h0, l0, h1, l1;
    split2(v.x, v.y, h0, l0);
    split2(v.z, v.w, h1, l1);
    char* pa = sm + row * APITCH + k4 * 8;
    *(uint2*)(pa + SA_HI) = make_uint2(h0, h1);
    *(uint2*)(pa + SA_LO) = make_uint2(l0, l1);
  }

  // Stage B: pre-converted g_Wh/g_Wl rows -> [k][n] smem (bulk 16B copies)
  for (int it = tid; it < 128 * 16; it += 256) {
    int k = it >> 4, c = it & 15;
    *(uint4*)(sm + SB_HI + k * APITCH + c * 16) =
        *(const uint4*)(g_Wh + k * 256 + gate * 128 + c * 8);
    *(uint4*)(sm + SB_LO + k * APITCH + c * 16) =
        *(const uint4*)(g_Wl + k * 256 + gate * 128 + c * 8);
  }
  __syncthreads();

  const int lane = tid & 31;
  const int warp = tid >> 5;
  const int wm = warp >> 1;   // 0..3 -> 32 rows each
  const int wn = warp & 1;    // 0..1 -> 64 cols each
  uint32_t sbase = (uint32_t)__cvta_generic_to_shared(sm);

  // ldmatrix lane address bases
  const uint32_t aoff = (uint32_t)((wm * 32 + (lane & 15)) * APITCH + (lane >> 4) * 16);
  const uint32_t boff = (uint32_t)((lane & 15) * APITCH + (wn * 64 + (lane >> 4) * 8) * 2);

  float acc[2][8][4];
#pragma unroll
  for (int mt = 0; mt < 2; mt++)
#pragma unroll
    for (int nt = 0; nt < 8; nt++)
#pragma unroll
      for (int j = 0; j < 4; j++) acc[mt][nt][j] = 0.f;

#pragma unroll
  for (int kt = 0; kt < 8; kt++) {
    uint32_t aH[2][4], aLo[2][4], bH[8][2], bLo[8][2];
    uint32_t ak = sbase + aoff + kt * 32;
    ldsm4(aH[0], ak + SA_HI);
    ldsm4(aH[1], ak + SA_HI + 16 * APITCH);
    ldsm4(aLo[0], ak + SA_LO);
    ldsm4(aLo[1], ak + SA_LO + 16 * APITCH);
    uint32_t bk = sbase + boff + kt * 16 * APITCH;
#pragma unroll
    for (int ntp = 0; ntp < 4; ntp++) {
      uint32_t r[4];
      ldsm4t(r, bk + SB_HI + ntp * 32);
      bH[2 * ntp][0] = r[0]; bH[2 * ntp][1] = r[1];
      bH[2 * ntp + 1][0] = r[2]; bH[2 * ntp + 1][1] = r[3];
      ldsm4t(r, bk + SB_LO + ntp * 32);
      bLo[2 * ntp][0] = r[0]; bLo[2 * ntp][1] = r[1];
      bLo[2 * ntp + 1][0] = r[2]; bLo[2 * ntp + 1][1] = r[3];
    }
#pragma unroll
    for (int mt = 0; mt < 2; mt++)
#pragma unroll
      for (int nt = 0; nt < 8; nt++) {
        mma_bf16(acc[mt][nt], aH[mt], bH[nt]);
        mma_bf16(acc[mt][nt], aH[mt], bLo[nt]);
        mma_bf16(acc[mt][nt], aLo[mt], bH[nt]);
      }
  }

  // Epilogue: store z (coalesced float2) + fused attention dots
  const int g = lane >> 2, tig = lane & 3;
  const float* atl = (const float*)(sm + SM_ATL);
  const float* atr = (const float*)(sm + SM_ATR);
  float pl[4] = {0, 0, 0, 0}, pr[4] = {0, 0, 0, 0};
#pragma unroll
  for (int mt = 0; mt < 2; mt++) {
    int r0 = m0 + wm * 32 + mt * 16 + g;
#pragma unroll
    for (int nt = 0; nt < 8; nt++) {
      int c = wn * 64 + nt * 8 + 2 * tig;
      float d0 = acc[mt][nt][0], d1 = acc[mt][nt][1];
      float d2 = acc[mt][nt][2], d3 = acc[mt][nt][3];
      pl[mt * 2 + 0] += d0 * atl[c] + d1 * atl[c + 1];
      pr[mt * 2 + 0] += d0 * atr[c] + d1 * atr[c + 1];
      pl[mt * 2 + 1] += d2 * atl[c] + d3 * atl[c + 1];
      pr[mt * 2 + 1] += d2 * atr[c] + d3 * atr[c + 1];
      if (r0 < NN) *(float2*)&g_z[r0][gate * 128 + c] = make_float2(d0, d1);
      if (r0 + 8 < NN) *(float2*)&g_z[r0 + 8][gate * 128 + c] = make_float2(d2, d3);
    }
  }
#pragma unroll
  for (int o = 1; o <= 2; o <<= 1)
#pragma unroll
    for (int i = 0; i < 4; i++) {
      pl[i] += __shfl_xor_sync(0xffffffffu, pl[i], o);
      pr[i] += __shfl_xor_sync(0xffffffffu, pr[i], o);
    }
  if (tig == 0) {
    float* el = (float*)(sm + SM_EL);
    float* er = (float*)(sm + SM_ER);
#pragma unroll
    for (int mt = 0; mt < 2; mt++)
#pragma unroll
      for (int hf = 0; hf < 2; hf++) {
        int r = wm * 32 + mt * 16 + g + hf * 8;
        el[r * 2 + wn] = pl[mt * 2 + hf];   // head = wn (cols 0-63 vs 64-127)
        er[r * 2 + wn] = pr[mt * 2 + hf];
      }
  }
  __syncthreads();
  if (tid < 128) {
    int node = m0 + tid;
    if (node < NN) {
      float* el = (float*)(sm + SM_EL);
      float* er = (float*)(sm + SM_ER);
      ((float2*)&g_attl[node])[gate] = make_float2(el[tid * 2 + 0], el[tid * 2 + 1]);
      ((float2*)&g_attr[node])[gate] = make_float2(er[tid * 2 + 0], er[tid * 2 + 1]);
    }
  }
}

// ============================ edge bucketing ===============================
// ex = exp(leaky_relu(el[src]+er[dst])); deposit (src, ex) into dst bucket.
// No denominator atomics: agg computes s = sum(ex) inline (division factors out).
__global__ __launch_bounds__(256) void k_edge1(const int* __restrict__ src,
                                               const int* __restrict__ dst) {
  int e = blockIdx.x * blockDim.x + threadIdx.x;
  if (e >= NE) return;
  int s = src[e], d = dst[e];
  float4 al = g_attl[s];
  float4 ar = g_attr[d];
  float v[4] = {al.x + ar.x, al.y + ar.y, al.z + ar.z, al.w + ar.w};
  float4 ex;
  float* exv = &ex.x;
#pragma unroll
  for (int k = 0; k < 4; k++) {
    float vv = v[k];
    vv = vv > 0.f ? vv : 0.2f * vv;
    exv[k] = __expf(vv);
  }
  int pos = atomicAdd(&g_deg[d], 1);
  if (pos < BSTRIDE) {
    g_bsrc[d * BSTRIDE + pos] = s;
    g_bex[d * BSTRIDE + pos] = ex;
  }
}

// ============================ aggregation ==================================
// One warp per (node, gate). Gather z[src], weight by ex, accumulate numerator
// and denominator in registers; normalize at end. Gate-c result exchanged via
// smem; gate-u warp writes the GRU output. No atomics.
__global__ __launch_bounds__(256) void k_agg(const float* __restrict__ h,
                                             const float* __restrict__ cb,
                                             const float* __restrict__ gb,
                                             float* __restrict__ out) {
  __shared__ float4 csm[4][32];
  const int wip = threadIdx.x >> 5;   // 0..7
  const int lane = threadIdx.x & 31;
  const int slot = wip >> 1;          // node slot in block
  const int gate = wip & 1;           // 0 = u, 1 = c
  const int node = blockIdx.x * 4 + slot;
  const bool valid = node < NN;
  const int cc = lane << 2;
  const bool head1 = cc >= 64;

  float4 num = make_float4(0.f, 0.f, 0.f, 0.f);
  float den = 0.f;
  if (valid) {
    int n = g_deg[node];
    n = n < BSTRIDE ? n : BSTRIDE;
    const int base = node * BSTRIDE;
    const float* exb = (const float*)&g_bex[base] + gate * 2;
    int i = 0;
    for (; i + 2 <= n; i += 2) {
      int s0 = g_bsrc[base + i];
      int s1 = g_bsrc[base + i + 1];
      float2 e0 = *(const float2*)(exb + (size_t)i * 4);
      float2 e1 = *(const float2*)(exb + (size_t)(i + 1) * 4);
      float4 z0 = *(const float4*)&g_z[s0][gate * 128 + cc];
      float4 z1 = *(const float4*)&g_z[s1][gate * 128 + cc];
      float w0 = head1 ? e0.y : e0.x;
      float w1 = head1 ? e1.y : e1.x;
      den += w0 + w1;
      num.x += w0 * z0.x + w1 * z1.x;
      num.y += w0 * z0.y + w1 * z1.y;
      num.z += w0 * z0.z + w1 * z1.z;
      num.w += w0 * z0.w + w1 * z1.w;
    }
    if (i < n) {
      int s0 = g_bsrc[base + i];
      float2 e0 = *(const float2*)(exb + (size_t)i * 4);
      float4 z0 = *(const float4*)&g_z[s0][gate * 128 + cc];
      float w0 = head1 ? e0.y : e0.x;
      den += w0;
      num.x += w0 * z0.x; num.y += w0 * z0.y;
      num.z += w0 * z0.z; num.w += w0 * z0.w;
    }
  }
  float inv = den > 0.f ? __frcp_rn(den) : 0.f;
  const int ob = (gate + 1) * 128 + cc;   // orig gate idx: u=1, c=2
  float4 cbv = *(const float4*)(cb + ob);
  float4 gbv = *(const float4*)(gb + ob);
  float4 gv;
  gv.x = 1.f / (1.f + __expf(-(num.x * inv + cbv.x + gbv.x)));
  gv.y = 1.f / (1.f + __expf(-(num.y * inv + cbv.y + gbv.y)));
  gv.z = 1.f / (1.f + __expf(-(num.z * inv + cbv.z + gbv.z)));
  gv.w = 1.f / (1.f + __expf(-(num.w * inv + cbv.w + gbv.w)));
  if (gate == 1) csm[slot][lane] = gv;
  __syncthreads();
  if (gate == 0 && valid) {
    float4 cv = csm[slot][lane];
    float4 hv = *(const float4*)(h + (size_t)node * 128 + cc);
    float4 o;
    o.x = gv.x * hv.x + (1.f - gv.x) * cv.x;
    o.y = gv.y * hv.y + (1.f - gv.y) * cv.y;
    o.z = gv.z * hv.z + (1.f - gv.z) * cv.z;
    o.w = gv.w * hv.w + (1.f - gv.w) * cv.w;
    *(float4*)(out + (size_t)node * 128 + cc) = o;
  }
}

// ---------------------------------------------------------------------------
extern "C" void kernel_launch(void* const* d_in, const int* in_sizes, int n_in,
                              void* d_out, int out_size) {
  const float* x      = (const float*)d_in[0];
  const float* h      = (const float*)d_in[1];
  const float* W      = (const float*)d_in[2];
  const float* attn_l = (const float*)d_in[3];
  const float* attn_r = (const float*)d_in[4];
  const float* conv_b = (const float*)d_in[5];
  const float* gate_b = (const float*)d_in[6];
  const int*   src    = (const int*)d_in[7];
  const int*   dst    = (const int*)d_in[8];
  float* out = (float*)d_out;

  static bool attr_set = false;
  if (!attr_set) {
    cudaFuncSetAttribute(k_gemm_mma, cudaFuncAttributeMaxDynamicSharedMemorySize,
                         SM_TOT);
    attr_set = true;
  }

  k_init<<<(NN + 255) / 256, 256>>>();
  k_prep<<<(128 * 256 + 255) / 256, 256>>>(W);
  dim3 ggrid(2, (NN + 127) / 128);   // gate fastest: paired CTAs share X in L2
  k_gemm_mma<<<ggrid, 256, SM_TOT>>>(x, attn_l, attn_r);
  k_edge1<<<(NE + 255) / 256, 256>>>(src, dst);
  k_agg<<<(NN + 3) / 4, 256>>>(h, conv_b, gate_b, out);
}

// round 6
// speedup vs baseline: 1.0831x; 1.0831x over previous
#include <cuda_runtime.h>
#include <cuda_fp16.h>
#include <cstdint>

#define NN 50000
#define NE 800000
#define BSTRIDE 64   // per-dst bucket cap; P(deg>=64)~1e-13 for Poisson(16)

// Scratch (allocation-free rule: __device__ globals)
__device__ __align__(16) __half g_zh[NN][256];  // z fp16: [node][gate*128+h*64+f]
__device__ float4 g_attl[NN];                   // el dots {u_h0,u_h1,c_h0,c_h1}
__device__ float4 g_attr[NN];                   // er dots
__device__ int    g_deg[NN];                    // incoming-degree cursor
__device__ int    g_bsrc[NN * BSTRIDE];         // bucket: src node per slot
__device__ __align__(16) float2 g_Wp[2][64][128]; // W k-packed: [gate][k/2][n]={w_2k,w_2k+1}

typedef unsigned long long ull;

#define FMA2(d, a, b) \
  asm("fma.rn.f32x2 %0, %1, %2, %0;" : "+l"(d) : "l"(a), "l"(b))

__device__ __forceinline__ float2 unpack2(ull v) {
  float2 r;
  asm("mov.b64 {%0, %1}, %2;" : "=f"(r.x), "=f"(r.y) : "l"(v));
  return r;
}

// ---------------------------------------------------------------------------
__global__ __launch_bounds__(256) void k_init() {
  int idx = blockIdx.x * blockDim.x + threadIdx.x;
  if (idx < NN) g_deg[idx] = 0;
}

// W[(128+gate*128+n)*128 + k] -> g_Wp[gate][k2][n] = (w_{2k2}, w_{2k2+1})
__global__ __launch_bounds__(256) void k_prep(const float* __restrict__ W) {
  int idx = blockIdx.x * blockDim.x + threadIdx.x;
  if (idx >= 2 * 64 * 128) return;
  int n = idx & 127, k2 = (idx >> 7) & 63, gate = idx >> 13;
  const float* wr = W + (size_t)(128 + gate * 128 + n) * 128;
  g_Wp[gate][k2][n] = make_float2(wr[2 * k2], wr[2 * k2 + 1]);
}

// ============================ f32x2 GEMM ===================================
// z[n][g*128+c] = sum_k x[n][k] * W[(1+g)*128+c][k], fp32 via packed f32x2
// (halves packed over k pairs, merged in epilogue). CTA: 128m x 128n x 128k.
// 512 threads, 8 rows x 4 cols each. Epilogue: fp16 z + fused attention dots.
__global__ __launch_bounds__(512) void k_gemm(const float* __restrict__ X,
                                              const float* __restrict__ AL,
                                              const float* __restrict__ AR) {
  __shared__ float2 As[2][8][128];   // [buf][k2][m]
  __shared__ float2 Bs[2][8][128];   // [buf][k2][n]
  __shared__ float satl[128], satr[128];
  __shared__ float4 sred[128];

  const int tid = threadIdx.x;
  const int gate = blockIdx.y;        // 0=u(orig 1), 1=c(orig 2)
  const int m0 = blockIdx.x * 128;

  if (tid < 128) {
    satl[tid] = AL[128 + gate * 128 + tid];
    satr[tid] = AR[128 + gate * 128 + tid];
  }

  // staging indices
  const int arow = tid & 127, akq = tid >> 7;          // A: 1 float4/thread
  const int bk2 = tid >> 6, bn2 = (tid & 63) * 2;      // B: 1 float4/thread
  const float* xrow = X + (size_t)(m0 + arow) * 128;
  const bool arow_ok = (m0 + arow) < NN;

#define STAGE(buf, s)                                                        \
  do {                                                                       \
    float4 v = make_float4(0.f, 0.f, 0.f, 0.f);                              \
    if (arow_ok) v = *(const float4*)(xrow + (s) * 16 + akq * 4);            \
    As[buf][akq * 2 + 0][arow] = make_float2(v.x, v.y);                      \
    As[buf][akq * 2 + 1][arow] = make_float2(v.z, v.w);                      \
    *(float4*)&Bs[buf][bk2][bn2] =                                           \
        *(const float4*)&g_Wp[gate][(s) * 8 + bk2][bn2];                     \
  } while (0)

  const int ty = tid >> 5;   // 0..15: rows ty*4..+3 and 64+ty*4..+3
  const int tx = tid & 31;   // cols tx*2,+1 and 64+tx*2,+1

  ull acc[8][4];
#pragma unroll
  for (int i = 0; i < 8; i++)
#pragma unroll
    for (int j = 0; j < 4; j++) acc[i][j] = 0ULL;

  STAGE(0, 0);
  __syncthreads();

  for (int s = 0; s < 8; s++) {
    if (s < 7) STAGE((s + 1) & 1, s + 1);
    const int b = s & 1;
#pragma unroll
    for (int k2 = 0; k2 < 8; k2++) {
      ulonglong2 a01 = *(const ulonglong2*)&As[b][k2][ty * 4];
      ulonglong2 a23 = *(const ulonglong2*)&As[b][k2][ty * 4 + 2];
      ulonglong2 a45 = *(const ulonglong2*)&As[b][k2][64 + ty * 4];
      ulonglong2 a67 = *(const ulonglong2*)&As[b][k2][64 + ty * 4 + 2];
      ulonglong2 b01 = *(const ulonglong2*)&Bs[b][k2][tx * 2];
      ulonglong2 b23 = *(const ulonglong2*)&Bs[b][k2][64 + tx * 2];
      ull Ar[8] = {a01.x, a01.y, a23.x, a23.y, a45.x, a45.y, a67.x, a67.y};
      ull Br[4] = {b01.x, b01.y, b23.x, b23.y};
#pragma unroll
      for (int i = 0; i < 8; i++) {
        FMA2(acc[i][0], Ar[i], Br[0]);
        FMA2(acc[i][1], Ar[i], Br[1]);
        FMA2(acc[i][2], Ar[i], Br[2]);
        FMA2(acc[i][3], Ar[i], Br[3]);
      }
    }
    __syncthreads();
  }

  // Epilogue: merge k halves, store fp16 z, fused attention dots
  const int c0 = tx * 2;
#pragma unroll
  for (int i = 0; i < 8; i++) {
    int rl = (i < 4) ? (ty * 4 + i) : (64 + ty * 4 + (i - 4));
    float2 p0 = unpack2(acc[i][0]);
    float2 p1 = unpack2(acc[i][1]);
    float2 p2 = unpack2(acc[i][2]);
    float2 p3 = unpack2(acc[i][3]);
    float z0 = p0.x + p0.y;       // col c0        (head 0)
    float z1 = p1.x + p1.y;       // col c0+1
    float z2 = p2.x + p2.y;       // col 64+c0     (head 1)
    float z3 = p3.x + p3.y;       // col 64+c0+1
    int node = m0 + rl;
    if (node < NN) {
      *(half2*)&g_zh[node][gate * 128 + c0] = __floats2half2_rn(z0, z1);
      *(half2*)&g_zh[node][gate * 128 + 64 + c0] = __floats2half2_rn(z2, z3);
    }
    float el0 = z0 * satl[c0] + z1 * satl[c0 + 1];
    float el1 = z2 * satl[64 + c0] + z3 * satl[64 + c0 + 1];
    float er0 = z0 * satr[c0] + z1 * satr[c0 + 1];
    float er1 = z2 * satr[64 + c0] + z3 * satr[64 + c0 + 1];
#pragma unroll
    for (int off = 16; off > 0; off >>= 1) {
      el0 += __shfl_xor_sync(0xffffffffu, el0, off);
      el1 += __shfl_xor_sync(0xffffffffu, el1, off);
      er0 += __shfl_xor_sync(0xffffffffu, er0, off);
      er1 += __shfl_xor_sync(0xffffffffu, er1, off);
    }
    if (tx == 0) sred[rl] = make_float4(el0, el1, er0, er1);
  }
  __syncthreads();
  if (tid < 128) {
    int node = m0 + tid;
    if (node < NN) {
      float4 v = sred[tid];
      ((float2*)&g_attl[node])[gate] = make_float2(v.x, v.y);
      ((float2*)&g_attr[node])[gate] = make_float2(v.z, v.w);
    }
  }
}

// ============================ edge bucketing ===============================
// Deposit src into dst's bucket. ex recomputed at fp32 in agg (attl/attr are
// L2-hot); softmax max-shift dropped (mathematically identical, |e|<~6).
__global__ __launch_bounds__(256) void k_bucket(const int* __restrict__ src,
                                                const int* __restrict__ dst) {
  int e = blockIdx.x * blockDim.x + threadIdx.x;
  if (e >= NE) return;
  int d = dst[e];
  int pos = atomicAdd(&g_deg[d], 1);
  if (pos < BSTRIDE) g_bsrc[d * BSTRIDE + pos] = src[e];
}

// ============================ aggregation ==================================
// One warp per node, BOTH gates. Preload srcs + per-entry exp() one-entry-per-
// lane; loop shuffles RAW components out (head select AFTER the shuffle —
// shuffling a head1-dependent ternary selects in the SOURCE lane, which was
// the R5 bug). Gathers fp16 z, accumulates num+den in registers; fused GRU
// epilogue. No atomics, no smem.
__global__ __launch_bounds__(256) void k_agg(const float* __restrict__ h,
                                             const float* __restrict__ cb,
                                             const float* __restrict__ gb,
                                             float* __restrict__ out) {
  const int node = (blockIdx.x * blockDim.x + threadIdx.x) >> 5;
  const int lane = threadIdx.x & 31;
  if (node >= NN) return;

  int n = g_deg[node];
  n = n < BSTRIDE ? n : BSTRIDE;
  const int base = node * BSTRIDE;
  const float4 ar = g_attr[node];

  // Preload: lane i owns entries i and i+32; compute their exp(leaky(.)) once.
  int sA = 0, sB = 0;
  float4 exA = make_float4(0.f, 0.f, 0.f, 0.f);
  float4 exB = make_float4(0.f, 0.f, 0.f, 0.f);
  if (lane < n) {
    sA = g_bsrc[base + lane];
    float4 al = g_attl[sA];
    float v0 = al.x + ar.x, v1 = al.y + ar.y, v2 = al.z + ar.z, v3 = al.w + ar.w;
    v0 = v0 > 0.f ? v0 : 0.2f * v0; v1 = v1 > 0.f ? v1 : 0.2f * v1;
    v2 = v2 > 0.f ? v2 : 0.2f * v2; v3 = v3 > 0.f ? v3 : 0.2f * v3;
    exA = make_float4(__expf(v0), __expf(v1), __expf(v2), __expf(v3));
  }
  if (lane + 32 < n) {
    sB = g_bsrc[base + lane + 32];
    float4 al = g_attl[sB];
    float v0 = al.x + ar.x, v1 = al.y + ar.y, v2 = al.z + ar.z, v3 = al.w + ar.w;
    v0 = v0 > 0.f ? v0 : 0.2f * v0; v1 = v1 > 0.f ? v1 : 0.2f * v1;
    v2 = v2 > 0.f ? v2 : 0.2f * v2; v3 = v3 > 0.f ? v3 : 0.2f * v3;
    exB = make_float4(__expf(v0), __expf(v1), __expf(v2), __expf(v3));
  }

  const int cc = lane << 2;           // feature base 0..124
  const bool head1 = lane >= 16;
  float4 accU = make_float4(0.f, 0.f, 0.f, 0.f);
  float4 accC = make_float4(0.f, 0.f, 0.f, 0.f);
  float denU = 0.f, denC = 0.f;

#define AGG_BODY(sreg, exreg, i)                                             \
  do {                                                                       \
    int s = __shfl_sync(0xffffffffu, sreg, i);                               \
    float ex_x = __shfl_sync(0xffffffffu, exreg.x, i);                       \
    float ex_y = __shfl_sync(0xffffffffu, exreg.y, i);                       \
    float ex_z = __shfl_sync(0xffffffffu, exreg.z, i);                       \
    float ex_w = __shfl_sync(0xffffffffu, exreg.w, i);                       \
    float e0 = head1 ? ex_y : ex_x;                                          \
    float e1 = head1 ? ex_w : ex_z;                                          \
    denU += e0; denC += e1;                                                  \
    uint2 zu = *(const uint2*)&g_zh[s][cc];                                  \
    uint2 zc = *(const uint2*)&g_zh[s][128 + cc];                            \
    float2 u01 = __half22float2(*(const half2*)&zu.x);                       \
    float2 u23 = __half22float2(*(const half2*)&zu.y);                       \
    float2 c01 = __half22float2(*(const half2*)&zc.x);                       \
    float2 c23 = __half22float2(*(const half2*)&zc.y);                       \
    accU.x += e0 * u01.x; accU.y += e0 * u01.y;                              \
    accU.z += e0 * u23.x; accU.w += e0 * u23.y;                              \
    accC.x += e1 * c01.x; accC.y += e1 * c01.y;                              \
    accC.z += e1 * c23.x; accC.w += e1 * c23.y;                              \
  } while (0)

  int nA = n < 32 ? n : 32;
  for (int i = 0; i < nA; i++) AGG_BODY(sA, exA, i);
  for (int i = 0; i < n - 32; i++) AGG_BODY(sB, exB, i);

  float invU = denU > 0.f ? __frcp_rn(denU) : 0.f;
  float invC = denC > 0.f ? __frcp_rn(denC) : 0.f;

  float4 cbu = *(const float4*)(cb + 128 + cc);
  float4 gbu = *(const float4*)(gb + 128 + cc);
  float4 cbc = *(const float4*)(cb + 256 + cc);
  float4 gbc = *(const float4*)(gb + 256 + cc);
  float4 hv  = *(const float4*)(h + (size_t)node * 128 + cc);

  float u0 = 1.f / (1.f + __expf(-(accU.x * invU + cbu.x + gbu.x)));
  float u1 = 1.f / (1.f + __expf(-(accU.y * invU + cbu.y + gbu.y)));
  float u2 = 1.f / (1.f + __expf(-(accU.z * invU + cbu.z + gbu.z)));
  float u3 = 1.f / (1.f + __expf(-(accU.w * invU + cbu.w + gbu.w)));
  float c0 = 1.f / (1.f + __expf(-(accC.x * invC + cbc.x + gbc.x)));
  float c1 = 1.f / (1.f + __expf(-(accC.y * invC + cbc.y + gbc.y)));
  float c2 = 1.f / (1.f + __expf(-(accC.z * invC + cbc.z + gbc.z)));
  float c3 = 1.f / (1.f + __expf(-(accC.w * invC + cbc.w + gbc.w)));

  float4 o;
  o.x = u0 * hv.x + (1.f - u0) * c0;
  o.y = u1 * hv.y + (1.f - u1) * c1;
  o.z = u2 * hv.z + (1.f - u2) * c2;
  o.w = u3 * hv.w + (1.f - u3) * c3;
  *(float4*)(out + (size_t)node * 128 + cc) = o;
}

// ---------------------------------------------------------------------------
extern "C" void kernel_launch(void* const* d_in, const int* in_sizes, int n_in,
                              void* d_out, int out_size) {
  const float* x      = (const float*)d_in[0];
  const float* h      = (const float*)d_in[1];
  const float* W      = (const float*)d_in[2];
  const float* attn_l = (const float*)d_in[3];
  const float* attn_r = (const float*)d_in[4];
  const float* conv_b = (const float*)d_in[5];
  const float* gate_b = (const float*)d_in[6];
  const int*   src    = (const int*)d_in[7];
  const int*   dst    = (const int*)d_in[8];
  float* out = (float*)d_out;

  k_init<<<(NN + 255) / 256, 256>>>();
  k_prep<<<(2 * 64 * 128 + 255) / 256, 256>>>(W);
  dim3 ggrid((NN + 127) / 128, 2);
  k_gemm<<<ggrid, 512>>>(x, attn_l, attn_r);
  k_bucket<<<(NE + 255) / 256, 256>>>(src, dst);
  k_agg<<<(NN * 32 + 255) / 256, 256>>>(h, conv_b, gate_b, out);
}

// round 8
// speedup vs baseline: 1.1779x; 1.0875x over previous
#include <cuda_runtime.h>
#include <cuda_fp16.h>
#include <cstdint>

#define NN 50000
#define NE 800000
#define BSTRIDE 64   // per-dst bucket cap; P(deg>=64)~1e-13 for Poisson(16)

// Scratch (allocation-free rule: __device__ globals)
__device__ __align__(16) __half g_zh[NN][256];  // z fp16: [node][gate*128+h*64+f]
__device__ float4 g_attl[NN];                   // el dots {u_h0,u_h1,c_h0,c_h1}
__device__ float4 g_attr[NN];                   // er dots
__device__ int    g_deg[NN];                    // incoming-degree cursor
__device__ int    g_bsrc[NN * BSTRIDE];         // bucket: src node per slot
// W column-pair packed: g_Wn[gate][k][n2] = (W[2*n2][k], W[2*n2+1][k])
__device__ __align__(16) float2 g_Wn[2][128][64];

typedef unsigned long long ull;

#define FMA2(d, a, b) \
  asm("fma.rn.f32x2 %0, %1, %2, %0;" : "+l"(d) : "l"(a), "l"(b))

__device__ __forceinline__ float2 unpack2(ull v) {
  float2 r;
  asm("mov.b64 {%0, %1}, %2;" : "=f"(r.x), "=f"(r.y) : "l"(v));
  return r;
}

// ---------------------------------------------------------------------------
// Combined: zero degree cursors + column-pair-pack weights.
__global__ __launch_bounds__(256) void k_prep(const float* __restrict__ W) {
  int idx = blockIdx.x * blockDim.x + threadIdx.x;
  if (idx < NN) g_deg[idx] = 0;
  if (idx >= 2 * 128 * 64) return;
  int n2 = idx & 63, k = (idx >> 6) & 127, gate = idx >> 13;
  const float* wb = W + (size_t)(128 + gate * 128 + 2 * n2) * 128 + k;
  g_Wn[gate][k][n2] = make_float2(wb[0], wb[128]);
}

// ============================ f32x2 GEMM ===================================
// z[n][g*128+c] = sum_k x[n][k] * W[(1+g)*128+c][k], fp32 via packed f32x2.
// Packing over COLUMN PAIRS (not k): acc ull = (col c, col c+1) final sums;
// A is stored smem-duplicated (x,x) so the loop has no pack instructions.
// CTA 128m x 128n x 128k, 256 threads, 8 rows x 8 cols (4 col-pairs) each
// -> 32 ull acc = 64 regs (no spills; 2 CTA/SM). 8-k double buffer, 16 stages.
__global__ __launch_bounds__(256, 2) void k_gemm(const float* __restrict__ X,
                                                 const float* __restrict__ AL,
                                                 const float* __restrict__ AR) {
  __shared__ float2 As[2][8][128];   // [buf][k][m] = (x,x) duplicated
  __shared__ float2 Bs[2][8][64];    // [buf][k][n2] = (w_c, w_c+1)
  __shared__ float satl[128], satr[128];
  __shared__ float4 sred[128];

  const int tid = threadIdx.x;
  const int gate = blockIdx.y;        // 0=u(orig 1), 1=c(orig 2)
  const int m0 = blockIdx.x * 128;

  if (tid < 128) {
    satl[tid] = AL[128 + gate * 128 + tid];
    satr[tid] = AR[128 + gate * 128 + tid];
  }

  // staging indices: A = 1 float4/thread (4 k dups), B = 1 float4/thread
  const int arow = tid & 127, akq = tid >> 7;     // akq in {0,1}
  const int bkl = tid >> 5, bn2 = (tid & 31) * 2; // bkl in {0..7}
  const float* xrow = X + (size_t)(m0 + arow) * 128;
  const bool arow_ok = (m0 + arow) < NN;

#define STAGE(buf, s)                                                        \
  do {                                                                       \
    float4 v = make_float4(0.f, 0.f, 0.f, 0.f);                              \
    if (arow_ok) v = *(const float4*)(xrow + (s) * 8 + akq * 4);             \
    As[buf][akq * 4 + 0][arow] = make_float2(v.x, v.x);                      \
    As[buf][akq * 4 + 1][arow] = make_float2(v.y, v.y);                      \
    As[buf][akq * 4 + 2][arow] = make_float2(v.z, v.z);                      \
    As[buf][akq * 4 + 3][arow] = make_float2(v.w, v.w);                      \
    *(float4*)&Bs[buf][bkl][bn2] =                                           \
        *(const float4*)&g_Wn[gate][(s) * 8 + bkl][bn2];                     \
  } while (0)

  const int ty = tid >> 4;   // 0..15: rows ty*4..+3 and 64+ty*4..+3
  const int tx = tid & 15;   // col-pair tx within each 16-pair quadrant

  ull acc[8][4];
#pragma unroll
  for (int i = 0; i < 8; i++)
#pragma unroll
    for (int j = 0; j < 4; j++) acc[i][j] = 0ULL;

  STAGE(0, 0);
  __syncthreads();

  for (int s = 0; s < 16; s++) {
    if (s < 15) STAGE((s + 1) & 1, s + 1);
    const int b = s & 1;
#pragma unroll
    for (int k = 0; k < 8; k++) {
      ull Ar[8], Br[4];
      Ar[0] = *(const ull*)&As[b][k][ty * 4 + 0];
      Ar[1] = *(const ull*)&As[b][k][ty * 4 + 1];
      Ar[2] = *(const ull*)&As[b][k][ty * 4 + 2];
      Ar[3] = *(const ull*)&As[b][k][ty * 4 + 3];
      Ar[4] = *(const ull*)&As[b][k][64 + ty * 4 + 0];
      Ar[5] = *(const ull*)&As[b][k][64 + ty * 4 + 1];
      Ar[6] = *(const ull*)&As[b][k][64 + ty * 4 + 2];
      Ar[7] = *(const ull*)&As[b][k][64 + ty * 4 + 3];
      Br[0] = *(const ull*)&Bs[b][k][tx];
      Br[1] = *(const ull*)&Bs[b][k][16 + tx];
      Br[2] = *(const ull*)&Bs[b][k][32 + tx];
      Br[3] = *(const ull*)&Bs[b][k][48 + tx];
#pragma unroll
      for (int i = 0; i < 8; i++) {
        FMA2(acc[i][0], Ar[i], Br[0]);
        FMA2(acc[i][1], Ar[i], Br[1]);
        FMA2(acc[i][2], Ar[i], Br[2]);
        FMA2(acc[i][3], Ar[i], Br[3]);
      }
    }
    __syncthreads();
  }

  // Epilogue: acc[i][j] = final (col c, col c+1) sums, c = j*32 + tx*2.
  // Coverage: 16 ty x 16 tx x (8 rows x 8 cols) = 128 x 128. Store fp16 z +
  // fused attention dots (head0 = j<2, head1 = j>=2).
  const int tx2 = tx * 2;
#pragma unroll
  for (int i = 0; i < 8; i++) {
    int rl = (i < 4) ? (ty * 4 + i) : (64 + ty * 4 + (i - 4));
    int node = m0 + rl;
    float el0 = 0.f, el1 = 0.f, er0 = 0.f, er1 = 0.f;
#pragma unroll
    for (int j = 0; j < 4; j++) {
      int c = j * 32 + tx2;
      float2 p = unpack2(acc[i][j]);
      if (node < NN)
        *(half2*)&g_zh[node][gate * 128 + c] = __floats2half2_rn(p.x, p.y);
      float l = p.x * satl[c] + p.y * satl[c + 1];
      float r = p.x * satr[c] + p.y * satr[c + 1];
      if (j < 2) { el0 += l; er0 += r; } else { el1 += l; er1 += r; }
    }
#pragma unroll
    for (int off = 1; off < 16; off <<= 1) {
      el0 += __shfl_xor_sync(0xffffffffu, el0, off);
      el1 += __shfl_xor_sync(0xffffffffu, el1, off);
      er0 += __shfl_xor_sync(0xffffffffu, er0, off);
      er1 += __shfl_xor_sync(0xffffffffu, er1, off);
    }
    if (tx == 0) sred[rl] = make_float4(el0, el1, er0, er1);
  }
  __syncthreads();
  if (tid < 128) {
    int node = m0 + tid;
    if (node < NN) {
      float4 v = sred[tid];
      ((float2*)&g_attl[node])[gate] = make_float2(v.x, v.y);
      ((float2*)&g_attr[node])[gate] = make_float2(v.z, v.w);
    }
  }
}

// ============================ edge bucketing ===============================
__global__ __launch_bounds__(256) void k_bucket(const int* __restrict__ src,
                                                const int* __restrict__ dst) {
  int e = blockIdx.x * blockDim.x + threadIdx.x;
  if (e >= NE) return;
  int d = dst[e];
  int pos = atomicAdd(&g_deg[d], 1);
  if (pos < BSTRIDE) g_bsrc[d * BSTRIDE + pos] = src[e];
}

// ============================ aggregation ==================================
// One warp per node, BOTH gates. Preload srcs + per-entry exp() one-entry-per-
// lane; loop shuffles RAW components (head select AFTER shuffle). Gathers fp16
// z, accumulates num+den in registers; fused GRU epilogue. No atomics.
__global__ __launch_bounds__(256) void k_agg(const float* __restrict__ h,
                                             const float* __restrict__ cb,
                                             const float* __restrict__ gb,
                                             float* __restrict__ out) {
  const int node = (blockIdx.x * blockDim.x + threadIdx.x) >> 5;
  const int lane = threadIdx.x & 31;
  if (node >= NN) return;

  int n = g_deg[node];
  n = n < BSTRIDE ? n : BSTRIDE;
  const int base = node * BSTRIDE;
  const float4 ar = g_attr[node];

  int sA = 0, sB = 0;
  float4 exA = make_float4(0.f, 0.f, 0.f, 0.f);
  float4 exB = make_float4(0.f, 0.f, 0.f, 0.f);
  if (lane < n) {
    sA = g_bsrc[base + lane];
    float4 al = g_attl[sA];
    float v0 = al.x + ar.x, v1 = al.y + ar.y, v2 = al.z + ar.z, v3 = al.w + ar.w;
    v0 = v0 > 0.f ? v0 : 0.2f * v0; v1 = v1 > 0.f ? v1 : 0.2f * v1;
    v2 = v2 > 0.f ? v2 : 0.2f * v2; v3 = v3 > 0.f ? v3 : 0.2f * v3;
    exA = make_float4(__expf(v0), __expf(v1), __expf(v2), __expf(v3));
  }
  if (lane + 32 < n) {
    sB = g_bsrc[base + lane + 32];
    float4 al = g_attl[sB];
    float v0 = al.x + ar.x, v1 = al.y + ar.y, v2 = al.z + ar.z, v3 = al.w + ar.w;
    v0 = v0 > 0.f ? v0 : 0.2f * v0; v1 = v1 > 0.f ? v1 : 0.2f * v1;
    v2 = v2 > 0.f ? v2 : 0.2f * v2; v3 = v3 > 0.f ? v3 : 0.2f * v3;
    exB = make_float4(__expf(v0), __expf(v1), __expf(v2), __expf(v3));
  }

  const int cc = lane << 2;
  const bool head1 = lane >= 16;
  float4 accU = make_float4(0.f, 0.f, 0.f, 0.f);
  float4 accC = make_float4(0.f, 0.f, 0.f, 0.f);
  float denU = 0.f, denC = 0.f;

#define AGG_BODY(sreg, exreg, i)                                             \
  do {                                                                       \
    int s = __shfl_sync(0xffffffffu, sreg, i);                               \
    float ex_x = __shfl_sync(0xffffffffu, exreg.x, i);                       \
    float ex_y = __shfl_sync(0xffffffffu, exreg.y, i);                       \
    float ex_z = __shfl_sync(0xffffffffu, exreg.z, i);                       \
    float ex_w = __shfl_sync(0xffffffffu, exreg.w, i);                       \
    float e0 = head1 ? ex_y : ex_x;                                          \
    float e1 = head1 ? ex_w : ex_z;                                          \
    denU += e0; denC += e1;                                                  \
    uint2 zu = *(const uint2*)&g_zh[s][cc];                                  \
    uint2 zc = *(const uint2*)&g_zh[s][128 + cc];                            \
    float2 u01 = __half22float2(*(const half2*)&zu.x);                       \
    float2 u23 = __half22float2(*(const half2*)&zu.y);                       \
    float2 c01 = __half22float2(*(const half2*)&zc.x);                       \
    float2 c23 = __half22float2(*(const half2*)&zc.y);                       \
    accU.x += e0 * u01.x; accU.y += e0 * u01.y;                              \
    accU.z += e0 * u23.x; accU.w += e0 * u23.y;                              \
    accC.x += e1 * c01.x; accC.y += e1 * c01.y;                              \
    accC.z += e1 * c23.x; accC.w += e1 * c23.y;                              \
  } while (0)

  int nA = n < 32 ? n : 32;
  for (int i = 0; i < nA; i++) AGG_BODY(sA, exA, i);
  for (int i = 0; i < n - 32; i++) AGG_BODY(sB, exB, i);

  float invU = denU > 0.f ? __frcp_rn(denU) : 0.f;
  float invC = denC > 0.f ? __frcp_rn(denC) : 0.f;

  float4 cbu = *(const float4*)(cb + 128 + cc);
  float4 gbu = *(const float4*)(gb + 128 + cc);
  float4 cbc = *(const float4*)(cb + 256 + cc);
  float4 gbc = *(const float4*)(gb + 256 + cc);
  float4 hv  = *(const float4*)(h + (size_t)node * 128 + cc);

  float u0 = 1.f / (1.f + __expf(-(accU.x * invU + cbu.x + gbu.x)));
  float u1 = 1.f / (1.f + __expf(-(accU.y * invU + cbu.y + gbu.y)));
  float u2 = 1.f / (1.f + __expf(-(accU.z * invU + cbu.z + gbu.z)));
  float u3 = 1.f / (1.f + __expf(-(accU.w * invU + cbu.w + gbu.w)));
  float c0 = 1.f / (1.f + __expf(-(accC.x * invC + cbc.x + gbc.x)));
  float c1 = 1.f / (1.f + __expf(-(accC.y * invC + cbc.y + gbc.y)));
  float c2 = 1.f / (1.f + __expf(-(accC.z * invC + cbc.z + gbc.z)));
  float c3 = 1.f / (1.f + __expf(-(accC.w * invC + cbc.w + gbc.w)));

  float4 o;
  o.x = u0 * hv.x + (1.f - u0) * c0;
  o.y = u1 * hv.y + (1.f - u1) * c1;
  o.z = u2 * hv.z + (1.f - u2) * c2;
  o.w = u3 * hv.w + (1.f - u3) * c3;
  *(float4*)(out + (size_t)node * 128 + cc) = o;
}

// ---------------------------------------------------------------------------
extern "C" void kernel_launch(void* const* d_in, const int* in_sizes, int n_in,
                              void* d_out, int out_size) {
  const float* x      = (const float*)d_in[0];
  const float* h      = (const float*)d_in[1];
  const float* W      = (const float*)d_in[2];
  const float* attn_l = (const float*)d_in[3];
  const float* attn_r = (const float*)d_in[4];
  const float* conv_b = (const float*)d_in[5];
  const float* gate_b = (const float*)d_in[6];
  const int*   src    = (const int*)d_in[7];
  const int*   dst    = (const int*)d_in[8];
  float* out = (float*)d_out;

  k_prep<<<(NN + 255) / 256, 256>>>(W);   // also zeroes g_deg
  dim3 ggrid((NN + 127) / 128, 2);
  k_gemm<<<ggrid, 256>>>(x, attn_l, attn_r);
  k_bucket<<<(NE + 255) / 256, 256>>>(src, dst);
  k_agg<<<(NN * 32 + 255) / 256, 256>>>(h, conv_b, gate_b, out);
}

// round 9
// speedup vs baseline: 1.2031x; 1.0214x over previous
#include <cuda_runtime.h>
#include <cuda_fp16.h>
#include <cstdint>

#define NN 50000
#define NE 800000
#define BSTRIDE 64   // per-dst bucket cap; P(deg>=64)~1e-13 for Poisson(16)

// Scratch (allocation-free rule: __device__ globals)
__device__ __align__(16) __half g_zh[NN][256];  // z fp16: [node][gate*128+h*64+f]
__device__ float4 g_attl[NN];                   // el dots {u_h0,u_h1,c_h0,c_h1}
__device__ float4 g_attr[NN];                   // er dots
__device__ int    g_deg[NN];                    // incoming-degree cursor
__device__ int    g_bsrc[NN * BSTRIDE];         // bucket: src node per slot
// W column-pair packed: g_Wn[gate][k][n2] = (W[2*n2][k], W[2*n2+1][k])
__device__ __align__(16) float2 g_Wn[2][128][64];

typedef unsigned long long ull;

#define FMA2(d, a, b) \
  asm("fma.rn.f32x2 %0, %1, %2, %0;" : "+l"(d) : "l"(a), "l"(b))

__device__ __forceinline__ float2 unpack2(ull v) {
  float2 r;
  asm("mov.b64 {%0, %1}, %2;" : "=f"(r.x), "=f"(r.y) : "l"(v));
  return r;
}

// ---------------------------------------------------------------------------
// Combined: zero degree cursors + column-pair-pack weights.
__global__ __launch_bounds__(256) void k_prep(const float* __restrict__ W) {
  int idx = blockIdx.x * blockDim.x + threadIdx.x;
  if (idx < NN) g_deg[idx] = 0;
  if (idx >= 2 * 128 * 64) return;
  int n2 = idx & 63, k = (idx >> 6) & 127, gate = idx >> 13;
  const float* wb = W + (size_t)(128 + gate * 128 + 2 * n2) * 128 + k;
  g_Wn[gate][k][n2] = make_float2(wb[0], wb[128]);
}

// ============================ f32x2 GEMM ===================================
// z[n][g*128+c] = sum_k x[n][k] * W[(1+g)*128+c][k], fp32, packed col pairs.
// CTA 128m x 128n x 128k, 256 threads, 8 rows x 8 cols each; 2 CTA/SM.
__global__ __launch_bounds__(256, 2) void k_gemm(const float* __restrict__ X,
                                                 const float* __restrict__ AL,
                                                 const float* __restrict__ AR) {
  __shared__ float2 As[2][8][128];   // [buf][k][m] = (x,x) duplicated
  __shared__ float2 Bs[2][8][64];    // [buf][k][n2] = (w_c, w_c+1)
  __shared__ float satl[128], satr[128];
  __shared__ float4 sred[128];

  const int tid = threadIdx.x;
  const int gate = blockIdx.y;        // 0=u(orig 1), 1=c(orig 2)
  const int m0 = blockIdx.x * 128;

  if (tid < 128) {
    satl[tid] = AL[128 + gate * 128 + tid];
    satr[tid] = AR[128 + gate * 128 + tid];
  }

  const int arow = tid & 127, akq = tid >> 7;     // akq in {0,1}
  const int bkl = tid >> 5, bn2 = (tid & 31) * 2; // bkl in {0..7}
  const float* xrow = X + (size_t)(m0 + arow) * 128;
  const bool arow_ok = (m0 + arow) < NN;

#define STAGE(buf, s)                                                        \
  do {                                                                       \
    float4 v = make_float4(0.f, 0.f, 0.f, 0.f);                              \
    if (arow_ok) v = *(const float4*)(xrow + (s) * 8 + akq * 4);             \
    As[buf][akq * 4 + 0][arow] = make_float2(v.x, v.x);                      \
    As[buf][akq * 4 + 1][arow] = make_float2(v.y, v.y);                      \
    As[buf][akq * 4 + 2][arow] = make_float2(v.z, v.z);                      \
    As[buf][akq * 4 + 3][arow] = make_float2(v.w, v.w);                      \
    *(float4*)&Bs[buf][bkl][bn2] =                                           \
        *(const float4*)&g_Wn[gate][(s) * 8 + bkl][bn2];                     \
  } while (0)

  const int ty = tid >> 4;   // 0..15
  const int tx = tid & 15;

  ull acc[8][4];
#pragma unroll
  for (int i = 0; i < 8; i++)
#pragma unroll
    for (int j = 0; j < 4; j++) acc[i][j] = 0ULL;

  STAGE(0, 0);
  __syncthreads();

  for (int s = 0; s < 16; s++) {
    if (s < 15) STAGE((s + 1) & 1, s + 1);
    const int b = s & 1;
#pragma unroll
    for (int k = 0; k < 8; k++) {
      ull Ar[8], Br[4];
      Ar[0] = *(const ull*)&As[b][k][ty * 4 + 0];
      Ar[1] = *(const ull*)&As[b][k][ty * 4 + 1];
      Ar[2] = *(const ull*)&As[b][k][ty * 4 + 2];
      Ar[3] = *(const ull*)&As[b][k][ty * 4 + 3];
      Ar[4] = *(const ull*)&As[b][k][64 + ty * 4 + 0];
      Ar[5] = *(const ull*)&As[b][k][64 + ty * 4 + 1];
      Ar[6] = *(const ull*)&As[b][k][64 + ty * 4 + 2];
      Ar[7] = *(const ull*)&As[b][k][64 + ty * 4 + 3];
      Br[0] = *(const ull*)&Bs[b][k][tx];
      Br[1] = *(const ull*)&Bs[b][k][16 + tx];
      Br[2] = *(const ull*)&Bs[b][k][32 + tx];
      Br[3] = *(const ull*)&Bs[b][k][48 + tx];
#pragma unroll
      for (int i = 0; i < 8; i++) {
        FMA2(acc[i][0], Ar[i], Br[0]);
        FMA2(acc[i][1], Ar[i], Br[1]);
        FMA2(acc[i][2], Ar[i], Br[2]);
        FMA2(acc[i][3], Ar[i], Br[3]);
      }
    }
    __syncthreads();
  }

  const int tx2 = tx * 2;
#pragma unroll
  for (int i = 0; i < 8; i++) {
    int rl = (i < 4) ? (ty * 4 + i) : (64 + ty * 4 + (i - 4));
    int node = m0 + rl;
    float el0 = 0.f, el1 = 0.f, er0 = 0.f, er1 = 0.f;
#pragma unroll
    for (int j = 0; j < 4; j++) {
      int c = j * 32 + tx2;
      float2 p = unpack2(acc[i][j]);
      if (node < NN)
        *(half2*)&g_zh[node][gate * 128 + c] = __floats2half2_rn(p.x, p.y);
      float l = p.x * satl[c] + p.y * satl[c + 1];
      float r = p.x * satr[c] + p.y * satr[c + 1];
      if (j < 2) { el0 += l; er0 += r; } else { el1 += l; er1 += r; }
    }
#pragma unroll
    for (int off = 1; off < 16; off <<= 1) {
      el0 += __shfl_xor_sync(0xffffffffu, el0, off);
      el1 += __shfl_xor_sync(0xffffffffu, el1, off);
      er0 += __shfl_xor_sync(0xffffffffu, er0, off);
      er1 += __shfl_xor_sync(0xffffffffu, er1, off);
    }
    if (tx == 0) sred[rl] = make_float4(el0, el1, er0, er1);
  }
  __syncthreads();
  if (tid < 128) {
    int node = m0 + tid;
    if (node < NN) {
      float4 v = sred[tid];
      ((float2*)&g_attl[node])[gate] = make_float2(v.x, v.y);
      ((float2*)&g_attr[node])[gate] = make_float2(v.z, v.w);
    }
  }
}

// ============================ edge bucketing ===============================
// 4 edges/thread via int4 loads -> 4 independent LDG->ATOMG->STG chains (MLP).
__global__ __launch_bounds__(256) void k_bucket(const int* __restrict__ src,
                                                const int* __restrict__ dst) {
  int t = blockIdx.x * blockDim.x + threadIdx.x;
  int e4 = t * 4;
  if (e4 >= NE) return;
  int4 s4 = *(const int4*)(src + e4);
  int4 d4 = *(const int4*)(dst + e4);
  int p0 = atomicAdd(&g_deg[d4.x], 1);
  int p1 = atomicAdd(&g_deg[d4.y], 1);
  int p2 = atomicAdd(&g_deg[d4.z], 1);
  int p3 = atomicAdd(&g_deg[d4.w], 1);
  if (p0 < BSTRIDE) g_bsrc[d4.x * BSTRIDE + p0] = s4.x;
  if (p1 < BSTRIDE) g_bsrc[d4.y * BSTRIDE + p1] = s4.y;
  if (p2 < BSTRIDE) g_bsrc[d4.z * BSTRIDE + p2] = s4.z;
  if (p3 < BSTRIDE) g_bsrc[d4.w * BSTRIDE + p3] = s4.w;
}

// ============================ aggregation ==================================
// 128-thread blocks = 2 nodes x 2 warps. Warp j of a node handles entries
// {j, j+2, j+4, ...} (interleaved so avg degree splits evenly). Preload stage:
// each lane computes one entry's (src, exp-quad) and stores to smem, with the
// quad PERMUTED to {u_h0, c_h0, u_h1, c_h1} so the loop's head-select is a
// single 8-byte offset (1 LDS.64). Partials merged across the warp pair via
// smem; warp 0 runs the fused GRU epilogue. No atomics, no shuffles in loop.
__global__ __launch_bounds__(128) void k_agg(const float* __restrict__ h,
                                             const float* __restrict__ cb,
                                             const float* __restrict__ gb,
                                             float* __restrict__ out) {
  __shared__ int    s_src[4][32];      // [wid][i] entry src (warp-private)
  __shared__ float4 s_ex[4][32];       // [wid][i] permuted exp quad
  __shared__ float4 s_pU[2][32];       // [slot] warp1 partial num (gate u)
  __shared__ float4 s_pC[2][32];       // [slot] warp1 partial num (gate c)
  __shared__ float2 s_pd[2][2];        // [slot][head] warp1 partial den (u,c)

  const int wid = threadIdx.x >> 5;    // 0..3
  const int lane = threadIdx.x & 31;
  const int slot = wid >> 1;           // node slot in block
  const int j = wid & 1;               // warp within pair
  const int node = blockIdx.x * 2 + slot;
  const bool valid = node < NN;

  int n = 0;
  if (valid) {
    n = g_deg[node];
    n = n < BSTRIDE ? n : BSTRIDE;
  }
  const int base = node * BSTRIDE;

  // Preload: lane l stages entry e = 2l + j (this warp's i = l slot).
  {
    int e = 2 * lane + j;
    if (valid && e < n) {
      int s = g_bsrc[base + e];
      float4 al = g_attl[s];
      float4 ar = g_attr[node];
      float v0 = al.x + ar.x, v1 = al.y + ar.y, v2 = al.z + ar.z, v3 = al.w + ar.w;
      v0 = v0 > 0.f ? v0 : 0.2f * v0; v1 = v1 > 0.f ? v1 : 0.2f * v1;
      v2 = v2 > 0.f ? v2 : 0.2f * v2; v3 = v3 > 0.f ? v3 : 0.2f * v3;
      s_src[wid][lane] = s;
      // permute to {u_h0, c_h0, u_h1, c_h1}
      s_ex[wid][lane] = make_float4(__expf(v0), __expf(v2), __expf(v1), __expf(v3));
    }
  }
  __syncwarp();

  const int cc = lane << 2;            // feature base 0..124
  const int hoff = (lane >= 16) ? 8 : 0;  // head-select byte offset
  float4 accU = make_float4(0.f, 0.f, 0.f, 0.f);
  float4 accC = make_float4(0.f, 0.f, 0.f, 0.f);
  float denU = 0.f, denC = 0.f;

  const int nj = valid ? ((n - j + 1) >> 1) : 0;   // this warp's entry count
  for (int i = 0; i < nj; i++) {
    int s = s_src[wid][i];
    float2 e01 = *(const float2*)((const char*)&s_ex[wid][i] + hoff);
    denU += e01.x; denC += e01.y;
    uint2 zu = *(const uint2*)&g_zh[s][cc];
    uint2 zc = *(const uint2*)&g_zh[s][128 + cc];
    float2 u01 = __half22float2(*(const half2*)&zu.x);
    float2 u23 = __half22float2(*(const half2*)&zu.y);
    float2 c01 = __half22float2(*(const half2*)&zc.x);
    float2 c23 = __half22float2(*(const half2*)&zc.y);
    accU.x += e01.x * u01.x; accU.y += e01.x * u01.y;
    accU.z += e01.x * u23.x; accU.w += e01.x * u23.y;
    accC.x += e01.y * c01.x; accC.y += e01.y * c01.y;
    accC.z += e01.y * c23.x; accC.w += e01.y * c23.y;
  }

  // Merge warp pair: warp 1 publishes partials, warp 0 finalizes.
  if (j == 1) {
    s_pU[slot][lane] = accU;
    s_pC[slot][lane] = accC;
    if ((lane & 15) == 0) s_pd[slot][lane >> 4] = make_float2(denU, denC);
  }
  __syncthreads();
  if (j == 0 && valid) {
    float4 oU = s_pU[slot][lane];
    float4 oC = s_pC[slot][lane];
    float2 od = s_pd[slot][lane >> 4];
    accU.x += oU.x; accU.y += oU.y; accU.z += oU.z; accU.w += oU.w;
    accC.x += oC.x; accC.y += oC.y; accC.z += oC.z; accC.w += oC.w;
    denU += od.x; denC += od.y;

    float invU = denU > 0.f ? __frcp_rn(denU) : 0.f;
    float invC = denC > 0.f ? __frcp_rn(denC) : 0.f;

    float4 cbu = *(const float4*)(cb + 128 + cc);
    float4 gbu = *(const float4*)(gb + 128 + cc);
    float4 cbc = *(const float4*)(cb + 256 + cc);
    float4 gbc = *(const float4*)(gb + 256 + cc);
    float4 hv  = *(const float4*)(h + (size_t)node * 128 + cc);

    float u0 = 1.f / (1.f + __expf(-(accU.x * invU + cbu.x + gbu.x)));
    float u1 = 1.f / (1.f + __expf(-(accU.y * invU + cbu.y + gbu.y)));
    float u2 = 1.f / (1.f + __expf(-(accU.z * invU + cbu.z + gbu.z)));
    float u3 = 1.f / (1.f + __expf(-(accU.w * invU + cbu.w + gbu.w)));
    float c0 = 1.f / (1.f + __expf(-(accC.x * invC + cbc.x + gbc.x)));
    float c1 = 1.f / (1.f + __expf(-(accC.y * invC + cbc.y + gbc.y)));
    float c2 = 1.f / (1.f + __expf(-(accC.z * invC + cbc.z + gbc.z)));
    float c3 = 1.f / (1.f + __expf(-(accC.w * invC + cbc.w + gbc.w)));

    float4 o;
    o.x = u0 * hv.x + (1.f - u0) * c0;
    o.y = u1 * hv.y + (1.f - u1) * c1;
    o.z = u2 * hv.z + (1.f - u2) * c2;
    o.w = u3 * hv.w + (1.f - u3) * c3;
    *(float4*)(out + (size_t)node * 128 + cc) = o;
  }
}

// ---------------------------------------------------------------------------
extern "C" void kernel_launch(void* const* d_in, const int* in_sizes, int n_in,
                              void* d_out, int out_size) {
  const float* x      = (const float*)d_in[0];
  const float* h      = (const float*)d_in[1];
  const float* W      = (const float*)d_in[2];
  const float* attn_l = (const float*)d_in[3];
  const float* attn_r = (const float*)d_in[4];
  const float* conv_b = (const float*)d_in[5];
  const float* gate_b = (const float*)d_in[6];
  const int*   src    = (const int*)d_in[7];
  const int*   dst    = (const int*)d_in[8];
  float* out = (float*)d_out;

  k_prep<<<(NN + 255) / 256, 256>>>(W);   // also zeroes g_deg
  dim3 ggrid((NN + 127) / 128, 2);
  k_gemm<<<ggrid, 256>>>(x, attn_l, attn_r);
  k_bucket<<<((NE / 4) + 255) / 256, 256>>>(src, dst);
  k_agg<<<(NN + 1) / 2, 128>>>(h, conv_b, gate_b, out);
}

// round 11
// speedup vs baseline: 1.7028x; 1.4154x over previous
#include <cuda_runtime.h>
#include <cuda_fp16.h>
#include <cstdint>

#define NN 50000
#define NE 800000
#define BSTRIDE 64   // per-dst bucket cap; P(deg>=64)~1e-13 for Poisson(16)

// Scratch (allocation-free rule: __device__ globals)
// z fp16 INTERLEAVED: [node][(f>>2)*8 + gate*4 + (f&3)]  (f in [0,128) per gate)
__device__ __align__(16) __half g_zh[NN][256];
__device__ float4 g_attl[NN];                   // el dots {u_h0,u_h1,c_h0,c_h1}
__device__ float4 g_attr[NN];                   // er dots
__device__ int    g_deg[NN];                    // incoming-degree cursor
__device__ int    g_bsrc[NN * BSTRIDE];         // bucket: src node per slot
__device__ __align__(16) __half g_Wh[128 * 256];  // W fp16 [k][n'=gate*128+c]
__device__ float g_v[8][128];  // attn-projected W: [side*4+gate*2+head][k]

// ============================ mma helpers ==================================
__device__ __forceinline__ void ldsm4(uint32_t* r, uint32_t addr) {
  asm volatile("ldmatrix.sync.aligned.m8n8.x4.shared.b16 {%0,%1,%2,%3}, [%4];"
               : "=r"(r[0]), "=r"(r[1]), "=r"(r[2]), "=r"(r[3]) : "r"(addr));
}
__device__ __forceinline__ void ldsm4t(uint32_t* r, uint32_t addr) {
  asm volatile("ldmatrix.sync.aligned.m8n8.x4.trans.shared.b16 {%0,%1,%2,%3}, [%4];"
               : "=r"(r[0]), "=r"(r[1]), "=r"(r[2]), "=r"(r[3]) : "r"(addr));
}
__device__ __forceinline__ void mma_f16(float* d, const uint32_t* a,
                                        const uint32_t* b) {
  asm volatile(
      "mma.sync.aligned.m16n8k16.row.col.f32.f16.f16.f32 "
      "{%0,%1,%2,%3}, {%4,%5,%6,%7}, {%8,%9}, {%0,%1,%2,%3};"
      : "+f"(d[0]), "+f"(d[1]), "+f"(d[2]), "+f"(d[3])
      : "r"(a[0]), "r"(a[1]), "r"(a[2]), "r"(a[3]), "r"(b[0]), "r"(b[1]));
}

// ---------------------------------------------------------------------------
// Combined prep: zero degree cursors; W -> fp16 [k][n']; v = W^T·attn (fp32).
__global__ __launch_bounds__(256) void k_prep(const float* __restrict__ W,
                                              const float* __restrict__ AL,
                                              const float* __restrict__ AR) {
  int idx = blockIdx.x * blockDim.x + threadIdx.x;
  if (idx < NN) g_deg[idx] = 0;
  if (idx < 128 * 256) {   // fp16 weight transpose-convert
    int n = idx & 255, k = idx >> 8;
    g_Wh[k * 256 + n] = __float2half_rn(W[(size_t)(128 + n) * 128 + k]);
  }
  if (idx < 1024) {        // v[s][k], s = side*4 + gate*2 + head
    int k = idx & 127, s = idx >> 7;
    int side = s >> 2, gate = (s >> 1) & 1, head = s & 1;
    const float* a = (side ? AR : AL) + (1 + gate) * 128 + head * 64;
    const float* wb = W + (size_t)(128 + gate * 128 + head * 64) * 128 + k;
    float acc = 0.f;
    for (int f = 0; f < 64; f++) acc += a[f] * wb[(size_t)f * 128];
    g_v[s][k] = acc;
  }
}

// ============================ fp16 mma GEMM ================================
// z[n][g*128+c] = sum_k x[n][k] * W[(1+g)*128+c][k], single fp16 product
// (attention logits are NOT derived from this — k_att computes them exactly).
// CTA: 128 nodes x 128 cols (one gate), K=128 staged. 8 warps of 32m x 64n.
#define APITCH 272
#define SA 0
#define SB 34816
#define SMT 69632

__global__ __launch_bounds__(256) void k_gemm(const float* __restrict__ X) {
  extern __shared__ char sm[];
  const int tid = threadIdx.x;
  const int gate = blockIdx.y;         // 0=u(orig 1), 1=c(orig 2)
  const int m0 = blockIdx.x * 128;

  // Stage A: X tile 128x128 f32 -> fp16, [m][k], pitch 272
  for (int it = tid; it < 128 * 32; it += 256) {
    int row = it >> 5, k4 = it & 31;
    int node = m0 + row;
    float4 v = make_float4(0.f, 0.f, 0.f, 0.f);
    if (node < NN) v = *(const float4*)(X + (size_t)node * 128 + k4 * 4);
    half2 h0 = __floats2half2_rn(v.x, v.y);
    half2 h1 = __floats2half2_rn(v.z, v.w);
    *(uint2*)(sm + SA + row * APITCH + k4 * 8) =
        make_uint2(*(uint32_t*)&h0, *(uint32_t*)&h1);
  }
  // Stage B: g_Wh[k][gate slice] -> [k][n] smem, 16 x 16B chunks per k row
  // (R10 bug: 8 chunks staged only 64 of 128 columns -> head-1 garbage)
  for (int it = tid; it < 128 * 16; it += 256) {
    int k = it >> 4, c16 = it & 15;
    *(uint4*)(sm + SB + k * APITCH + c16 * 16) =
        *(const uint4*)(g_Wh + k * 256 + gate * 128 + c16 * 8);
  }
  __syncthreads();

  const int lane = tid & 31;
  const int warp = tid >> 5;
  const int wm = warp >> 1;   // 0..3 -> 32 rows each
  const int wn = warp & 1;    // 0..1 -> 64 cols each
  uint32_t sbase = (uint32_t)__cvta_generic_to_shared(sm);

  const uint32_t aoff = (uint32_t)((wm * 32 + (lane & 15)) * APITCH + (lane >> 4) * 16);
  const uint32_t boff = (uint32_t)((lane & 15) * APITCH + (wn * 64 + (lane >> 4) * 8) * 2);

  float acc[2][8][4];
#pragma unroll
  for (int mt = 0; mt < 2; mt++)
#pragma unroll
    for (int nt = 0; nt < 8; nt++)
#pragma unroll
      for (int j = 0; j < 4; j++) acc[mt][nt][j] = 0.f;

#pragma unroll
  for (int kt = 0; kt < 8; kt++) {
    uint32_t aF[2][4], bF[8][2];
    uint32_t ak = sbase + SA + aoff + kt * 32;
    ldsm4(aF[0], ak);
    ldsm4(aF[1], ak + 16 * APITCH);
    uint32_t bk = sbase + SB + boff + kt * 16 * APITCH;
#pragma unroll
    for (int ntp = 0; ntp < 4; ntp++) {
      uint32_t r[4];
      ldsm4t(r, bk + ntp * 32);
      bF[2 * ntp][0] = r[0]; bF[2 * ntp][1] = r[1];
      bF[2 * ntp + 1][0] = r[2]; bF[2 * ntp + 1][1] = r[3];
    }
#pragma unroll
    for (int mt = 0; mt < 2; mt++)
#pragma unroll
      for (int nt = 0; nt < 8; nt++) mma_f16(acc[mt][nt], aF[mt], bF[nt]);
  }

  // Epilogue: store z fp16 interleaved. Row r holds cols (c,c+1) per tile;
  // c = wn*64+nt*8+2*tig (c&3 in {0,2}) -> pos = (c>>2)*8 + gate*4 + (c&3).
  const int g = lane >> 2, tig = lane & 3;
#pragma unroll
  for (int mt = 0; mt < 2; mt++) {
    int r0 = m0 + wm * 32 + mt * 16 + g;
#pragma unroll
    for (int nt = 0; nt < 8; nt++) {
      int c = wn * 64 + nt * 8 + 2 * tig;
      int pos = ((c >> 2) << 3) + gate * 4 + (c & 3);
      half2 v01 = __floats2half2_rn(acc[mt][nt][0], acc[mt][nt][1]);
      half2 v23 = __floats2half2_rn(acc[mt][nt][2], acc[mt][nt][3]);
      if (r0 < NN) *(half2*)&g_zh[r0][pos] = v01;
      if (r0 + 8 < NN) *(half2*)&g_zh[r0 + 8][pos] = v23;
    }
  }
}

// ============================ exact attention dots =========================
// el/er[node][s] = sum_k x[node][k] * v[s][k], full fp32. One warp per node.
__global__ __launch_bounds__(256) void k_att(const float* __restrict__ X) {
  int node = (blockIdx.x * blockDim.x + threadIdx.x) >> 5;
  int lane = threadIdx.x & 31;
  if (node >= NN) return;
  float4 xv = *(const float4*)(X + (size_t)node * 128 + lane * 4);
  float p[8];
#pragma unroll
  for (int s = 0; s < 8; s++) {
    float4 vv = *(const float4*)&g_v[s][lane * 4];
    p[s] = xv.x * vv.x + xv.y * vv.y + xv.z * vv.z + xv.w * vv.w;
  }
#pragma unroll
  for (int off = 16; off > 0; off >>= 1)
#pragma unroll
    for (int s = 0; s < 8; s++) p[s] += __shfl_xor_sync(0xffffffffu, p[s], off);
  if (lane == 0) {
    g_attl[node] = make_float4(p[0], p[1], p[2], p[3]);  // {u_h0,u_h1,c_h0,c_h1}
    g_attr[node] = make_float4(p[4], p[5], p[6], p[7]);
  }
}

// ============================ edge bucketing ===============================
__global__ __launch_bounds__(256) void k_bucket(const int* __restrict__ src,
                                                const int* __restrict__ dst) {
  int t = blockIdx.x * blockDim.x + threadIdx.x;
  int e4 = t * 4;
  if (e4 >= NE) return;
  int4 s4 = *(const int4*)(src + e4);
  int4 d4 = *(const int4*)(dst + e4);
  int p0 = atomicAdd(&g_deg[d4.x], 1);
  int p1 = atomicAdd(&g_deg[d4.y], 1);
  int p2 = atomicAdd(&g_deg[d4.z], 1);
  int p3 = atomicAdd(&g_deg[d4.w], 1);
  if (p0 < BSTRIDE) g_bsrc[d4.x * BSTRIDE + p0] = s4.x;
  if (p1 < BSTRIDE) g_bsrc[d4.y * BSTRIDE + p1] = s4.y;
  if (p2 < BSTRIDE) g_bsrc[d4.z * BSTRIDE + p2] = s4.z;
  if (p3 < BSTRIDE) g_bsrc[d4.w * BSTRIDE + p3] = s4.w;
}

// ============================ aggregation ==================================
// 2 nodes x 2 warps per 128-thread block; interleaved entries; smem-staged
// permuted exp quads; ONE LDG.128 per entry (interleaved z). No atomics.
__global__ __launch_bounds__(128) void k_agg(const float* __restrict__ h,
                                             const float* __restrict__ cb,
                                             const float* __restrict__ gb,
                                             float* __restrict__ out) {
  __shared__ int    s_src[4][32];
  __shared__ float4 s_ex[4][32];
  __shared__ float4 s_pU[2][32];
  __shared__ float4 s_pC[2][32];
  __shared__ float2 s_pd[2][2];

  const int wid = threadIdx.x >> 5;
  const int lane = threadIdx.x & 31;
  const int slot = wid >> 1;
  const int j = wid & 1;
  const int node = blockIdx.x * 2 + slot;
  const bool valid = node < NN;

  int n = 0;
  if (valid) {
    n = g_deg[node];
    n = n < BSTRIDE ? n : BSTRIDE;
  }
  const int base = node * BSTRIDE;

  {
    int e = 2 * lane + j;
    if (valid && e < n) {
      int s = g_bsrc[base + e];
      float4 al = g_attl[s];
      float4 ar = g_attr[node];
      float v0 = al.x + ar.x, v1 = al.y + ar.y, v2 = al.z + ar.z, v3 = al.w + ar.w;
      v0 = v0 > 0.f ? v0 : 0.2f * v0; v1 = v1 > 0.f ? v1 : 0.2f * v1;
      v2 = v2 > 0.f ? v2 : 0.2f * v2; v3 = v3 > 0.f ? v3 : 0.2f * v3;
      s_src[wid][lane] = s;
      // permute to {u_h0, c_h0, u_h1, c_h1}
      s_ex[wid][lane] = make_float4(__expf(v0), __expf(v2), __expf(v1), __expf(v3));
    }
  }
  __syncwarp();

  const int hoff = (lane >= 16) ? 8 : 0;
  float4 accU = make_float4(0.f, 0.f, 0.f, 0.f);
  float4 accC = make_float4(0.f, 0.f, 0.f, 0.f);
  float denU = 0.f, denC = 0.f;

  const int nj = valid ? ((n - j + 1) >> 1) : 0;
  for (int i = 0; i < nj; i++) {
    int s = s_src[wid][i];
    float2 e01 = *(const float2*)((const char*)&s_ex[wid][i] + hoff);
    denU += e01.x; denC += e01.y;
    uint4 zz = *(const uint4*)&g_zh[s][lane * 8];   // {u01,u23,c01,c23}
    float2 u01 = __half22float2(*(const half2*)&zz.x);
    float2 u23 = __half22float2(*(const half2*)&zz.y);
    float2 c01 = __half22float2(*(const half2*)&zz.z);
    float2 c23 = __half22float2(*(const half2*)&zz.w);
    accU.x += e01.x * u01.x; accU.y += e01.x * u01.y;
    accU.z += e01.x * u23.x; accU.w += e01.x * u23.y;
    accC.x += e01.y * c01.x; accC.y += e01.y * c01.y;
    accC.z += e01.y * c23.x; accC.w += e01.y * c23.y;
  }

  if (j == 1) {
    s_pU[slot][lane] = accU;
    s_pC[slot][lane] = accC;
    if ((lane & 15) == 0) s_pd[slot][lane >> 4] = make_float2(denU, denC);
  }
  __syncthreads();
  if (j == 0 && valid) {
    float4 oU = s_pU[slot][lane];
    float4 oC = s_pC[slot][lane];
    float2 od = s_pd[slot][lane >> 4];
    accU.x += oU.x; accU.y += oU.y; accU.z += oU.z; accU.w += oU.w;
    accC.x += oC.x; accC.y += oC.y; accC.z += oC.z; accC.w += oC.w;
    denU += od.x; denC += od.y;

    float invU = denU > 0.f ? __frcp_rn(denU) : 0.f;
    float invC = denC > 0.f ? __frcp_rn(denC) : 0.f;
    const int cc = lane << 2;

    float4 cbu = *(const float4*)(cb + 128 + cc);
    float4 gbu = *(const float4*)(gb + 128 + cc);
    float4 cbc = *(const float4*)(cb + 256 + cc);
    float4 gbc = *(const float4*)(gb + 256 + cc);
    float4 hv  = *(const float4*)(h + (size_t)node * 128 + cc);

    float u0 = 1.f / (1.f + __expf(-(accU.x * invU + cbu.x + gbu.x)));
    float u1 = 1.f / (1.f + __expf(-(accU.y * invU + cbu.y + gbu.y)));
    float u2 = 1.f / (1.f + __expf(-(accU.z * invU + cbu.z + gbu.z)));
    float u3 = 1.f / (1.f + __expf(-(accU.w * invU + cbu.w + gbu.w)));
    float c0 = 1.f / (1.f + __expf(-(accC.x * invC + cbc.x + gbc.x)));
    float c1 = 1.f / (1.f + __expf(-(accC.y * invC + cbc.y + gbc.y)));
    float c2 = 1.f / (1.f + __expf(-(accC.z * invC + cbc.z + gbc.z)));
    float c3 = 1.f / (1.f + __expf(-(accC.w * invC + cbc.w + gbc.w)));

    float4 o;
    o.x = u0 * hv.x + (1.f - u0) * c0;
    o.y = u1 * hv.y + (1.f - u1) * c1;
    o.z = u2 * hv.z + (1.f - u2) * c2;
    o.w = u3 * hv.w + (1.f - u3) * c3;
    *(float4*)(out + (size_t)node * 128 + cc) = o;
  }
}

// ---------------------------------------------------------------------------
extern "C" void kernel_launch(void* const* d_in, const int* in_sizes, int n_in,
                              void* d_out, int out_size) {
  const float* x      = (const float*)d_in[0];
  const float* h      = (const float*)d_in[1];
  const float* W      = (const float*)d_in[2];
  const float* attn_l = (const float*)d_in[3];
  const float* attn_r = (const float*)d_in[4];
  const float* conv_b = (const float*)d_in[5];
  const float* gate_b = (const float*)d_in[6];
  const int*   src    = (const int*)d_in[7];
  const int*   dst    = (const int*)d_in[8];
  float* out = (float*)d_out;

  static bool attr_set = false;
  if (!attr_set) {
    cudaFuncSetAttribute(k_gemm, cudaFuncAttributeMaxDynamicSharedMemorySize, SMT);
    attr_set = true;
  }

  k_prep<<<(NN + 255) / 256, 256>>>(W, attn_l, attn_r);
  dim3 ggrid((NN + 127) / 128, 2);
  k_gemm<<<ggrid, 256, SMT>>>(x);
  k_att<<<(NN * 32 + 255) / 256, 256>>>(x);
  k_bucket<<<((NE / 4) + 255) / 256, 256>>>(src, dst);
  k_agg<<<(NN + 1) / 2, 128>>>(h, conv_b, gate_b, out);
}

// round 12
// speedup vs baseline: 1.7986x; 1.0562x over previous
#include <cuda_runtime.h>
#include <cuda_fp16.h>
#include <cstdint>

#define NN 50000
#define NE 800000
#define BSTRIDE 64   // per-dst bucket cap; P(deg>=64)~1e-13 for Poisson(16)

// Scratch (allocation-free rule: __device__ globals)
// z fp16 INTERLEAVED: [node][(f>>2)*8 + gate*4 + (f&3)]  (f in [0,128) per gate)
__device__ __align__(16) __half g_zh[NN][256];
__device__ float4 g_attl[NN];                   // el dots {u_h0,u_h1,c_h0,c_h1}
__device__ float4 g_attr[NN];                   // er dots
__device__ int    g_deg[NN];                    // incoming-degree cursor
__device__ int    g_bsrc[NN * BSTRIDE];         // bucket: src node per slot
__device__ __align__(16) __half g_Wh[128 * 256];  // W fp16 [k][n'=gate*128+c]
__device__ float g_v[8][128];  // attn-projected W: [side*4+gate*2+head][k]

// ============================ mma helpers ==================================
__device__ __forceinline__ void ldsm4(uint32_t* r, uint32_t addr) {
  asm volatile("ldmatrix.sync.aligned.m8n8.x4.shared.b16 {%0,%1,%2,%3}, [%4];"
               : "=r"(r[0]), "=r"(r[1]), "=r"(r[2]), "=r"(r[3]) : "r"(addr));
}
__device__ __forceinline__ void ldsm4t(uint32_t* r, uint32_t addr) {
  asm volatile("ldmatrix.sync.aligned.m8n8.x4.trans.shared.b16 {%0,%1,%2,%3}, [%4];"
               : "=r"(r[0]), "=r"(r[1]), "=r"(r[2]), "=r"(r[3]) : "r"(addr));
}
__device__ __forceinline__ void mma_f16(float* d, const uint32_t* a,
                                        const uint32_t* b) {
  asm volatile(
      "mma.sync.aligned.m16n8k16.row.col.f32.f16.f16.f32 "
      "{%0,%1,%2,%3}, {%4,%5,%6,%7}, {%8,%9}, {%0,%1,%2,%3};"
      : "+f"(d[0]), "+f"(d[1]), "+f"(d[2]), "+f"(d[3])
      : "r"(a[0]), "r"(a[1]), "r"(a[2]), "r"(a[3]), "r"(b[0]), "r"(b[1]));
}

// ---------------------------------------------------------------------------
// Combined prep: zero degree cursors; W -> fp16 [k][n']; v = W^T·attn (fp32).
__global__ __launch_bounds__(256) void k_prep(const float* __restrict__ W,
                                              const float* __restrict__ AL,
                                              const float* __restrict__ AR) {
  int idx = blockIdx.x * blockDim.x + threadIdx.x;
  if (idx < NN) g_deg[idx] = 0;
  if (idx < 128 * 256) {   // fp16 weight transpose-convert
    int n = idx & 255, k = idx >> 8;
    g_Wh[k * 256 + n] = __float2half_rn(W[(size_t)(128 + n) * 128 + k]);
  }
  if (idx < 1024) {        // v[s][k], s = side*4 + gate*2 + head
    int k = idx & 127, s = idx >> 7;
    int side = s >> 2, gate = (s >> 1) & 1, head = s & 1;
    const float* a = (side ? AR : AL) + (1 + gate) * 128 + head * 64;
    const float* wb = W + (size_t)(128 + gate * 128 + head * 64) * 128 + k;
    float acc = 0.f;
    for (int f = 0; f < 64; f++) acc += a[f] * wb[(size_t)f * 128];
    g_v[s][k] = acc;
  }
}

// ============================ fp16 mma GEMM ================================
// z[n][g*128+c] = sum_k x[n][k] * W[(1+g)*128+c][k], single fp16 product
// (attention logits are NOT derived from this — k_att computes them exactly).
// CTA: 128 nodes x 128 cols (one gate), K=128 staged. 8 warps of 32m x 64n.
#define APITCH 272
#define SA 0
#define SB 34816
#define SMT 69632

__global__ __launch_bounds__(256) void k_gemm(const float* __restrict__ X) {
  extern __shared__ char sm[];
  const int tid = threadIdx.x;
  const int gate = blockIdx.y;         // 0=u(orig 1), 1=c(orig 2)
  const int m0 = blockIdx.x * 128;

  // Stage A: X tile 128x128 f32 -> fp16, [m][k], pitch 272
  for (int it = tid; it < 128 * 32; it += 256) {
    int row = it >> 5, k4 = it & 31;
    int node = m0 + row;
    float4 v = make_float4(0.f, 0.f, 0.f, 0.f);
    if (node < NN) v = *(const float4*)(X + (size_t)node * 128 + k4 * 4);
    half2 h0 = __floats2half2_rn(v.x, v.y);
    half2 h1 = __floats2half2_rn(v.z, v.w);
    *(uint2*)(sm + SA + row * APITCH + k4 * 8) =
        make_uint2(*(uint32_t*)&h0, *(uint32_t*)&h1);
  }
  // Stage B: g_Wh[k][gate slice] -> [k][n] smem, 16 x 16B chunks per k row
  for (int it = tid; it < 128 * 16; it += 256) {
    int k = it >> 4, c16 = it & 15;
    *(uint4*)(sm + SB + k * APITCH + c16 * 16) =
        *(const uint4*)(g_Wh + k * 256 + gate * 128 + c16 * 8);
  }
  __syncthreads();

  const int lane = tid & 31;
  const int warp = tid >> 5;
  const int wm = warp >> 1;   // 0..3 -> 32 rows each
  const int wn = warp & 1;    // 0..1 -> 64 cols each
  uint32_t sbase = (uint32_t)__cvta_generic_to_shared(sm);

  const uint32_t aoff = (uint32_t)((wm * 32 + (lane & 15)) * APITCH + (lane >> 4) * 16);
  const uint32_t boff = (uint32_t)((lane & 15) * APITCH + (wn * 64 + (lane >> 4) * 8) * 2);

  float acc[2][8][4];
#pragma unroll
  for (int mt = 0; mt < 2; mt++)
#pragma unroll
    for (int nt = 0; nt < 8; nt++)
#pragma unroll
      for (int j = 0; j < 4; j++) acc[mt][nt][j] = 0.f;

#pragma unroll
  for (int kt = 0; kt < 8; kt++) {
    uint32_t aF[2][4], bF[8][2];
    uint32_t ak = sbase + SA + aoff + kt * 32;
    ldsm4(aF[0], ak);
    ldsm4(aF[1], ak + 16 * APITCH);
    uint32_t bk = sbase + SB + boff + kt * 16 * APITCH;
#pragma unroll
    for (int ntp = 0; ntp < 4; ntp++) {
      uint32_t r[4];
      ldsm4t(r, bk + ntp * 32);
      bF[2 * ntp][0] = r[0]; bF[2 * ntp][1] = r[1];
      bF[2 * ntp + 1][0] = r[2]; bF[2 * ntp + 1][1] = r[3];
    }
#pragma unroll
    for (int mt = 0; mt < 2; mt++)
#pragma unroll
      for (int nt = 0; nt < 8; nt++) mma_f16(acc[mt][nt], aF[mt], bF[nt]);
  }

  // Epilogue: store z fp16 interleaved. pos = (c>>2)*8 + gate*4 + (c&3).
  const int g = lane >> 2, tig = lane & 3;
#pragma unroll
  for (int mt = 0; mt < 2; mt++) {
    int r0 = m0 + wm * 32 + mt * 16 + g;
#pragma unroll
    for (int nt = 0; nt < 8; nt++) {
      int c = wn * 64 + nt * 8 + 2 * tig;
      int pos = ((c >> 2) << 3) + gate * 4 + (c & 3);
      half2 v01 = __floats2half2_rn(acc[mt][nt][0], acc[mt][nt][1]);
      half2 v23 = __floats2half2_rn(acc[mt][nt][2], acc[mt][nt][3]);
      if (r0 < NN) *(half2*)&g_zh[r0][pos] = v01;
      if (r0 + 8 < NN) *(half2*)&g_zh[r0 + 8][pos] = v23;
    }
  }
}

// ============================ exact attention dots =========================
__global__ __launch_bounds__(256) void k_att(const float* __restrict__ X) {
  int node = (blockIdx.x * blockDim.x + threadIdx.x) >> 5;
  int lane = threadIdx.x & 31;
  if (node >= NN) return;
  float4 xv = *(const float4*)(X + (size_t)node * 128 + lane * 4);
  float p[8];
#pragma unroll
  for (int s = 0; s < 8; s++) {
    float4 vv = *(const float4*)&g_v[s][lane * 4];
    p[s] = xv.x * vv.x + xv.y * vv.y + xv.z * vv.z + xv.w * vv.w;
  }
#pragma unroll
  for (int off = 16; off > 0; off >>= 1)
#pragma unroll
    for (int s = 0; s < 8; s++) p[s] += __shfl_xor_sync(0xffffffffu, p[s], off);
  if (lane == 0) {
    g_attl[node] = make_float4(p[0], p[1], p[2], p[3]);  // {u_h0,u_h1,c_h0,c_h1}
    g_attr[node] = make_float4(p[4], p[5], p[6], p[7]);
  }
}

// ============================ edge bucketing ===============================
__global__ __launch_bounds__(256) void k_bucket(const int* __restrict__ src,
                                                const int* __restrict__ dst) {
  int t = blockIdx.x * blockDim.x + threadIdx.x;
  int e4 = t * 4;
  if (e4 >= NE) return;
  int4 s4 = *(const int4*)(src + e4);
  int4 d4 = *(const int4*)(dst + e4);
  int p0 = atomicAdd(&g_deg[d4.x], 1);
  int p1 = atomicAdd(&g_deg[d4.y], 1);
  int p2 = atomicAdd(&g_deg[d4.z], 1);
  int p3 = atomicAdd(&g_deg[d4.w], 1);
  if (p0 < BSTRIDE) g_bsrc[d4.x * BSTRIDE + p0] = s4.x;
  if (p1 < BSTRIDE) g_bsrc[d4.y * BSTRIDE + p1] = s4.y;
  if (p2 < BSTRIDE) g_bsrc[d4.z * BSTRIDE + p2] = s4.z;
  if (p3 < BSTRIDE) g_bsrc[d4.w * BSTRIDE + p3] = s4.w;
}

// ============================ aggregation ==================================
// 2 nodes x 2 warps per 128-thread block; interleaved entries; smem-staged
// permuted exp quads; ONE LDG.128 per entry (interleaved z). No atomics.
__global__ __launch_bounds__(128) void k_agg(const float* __restrict__ h,
                                             const float* __restrict__ cb,
                                             const float* __restrict__ gb,
                                             float* __restrict__ out) {
  __shared__ int    s_src[4][32];
  __shared__ float4 s_ex[4][32];
  __shared__ float4 s_pU[2][32];
  __shared__ float4 s_pC[2][32];
  __shared__ float2 s_pd[2][2];

  const int wid = threadIdx.x >> 5;
  const int lane = threadIdx.x & 31;
  const int slot = wid >> 1;
  const int j = wid & 1;
  const int node = blockIdx.x * 2 + slot;
  const bool valid = node < NN;

  int n = 0;
  if (valid) {
    n = g_deg[node];
    n = n < BSTRIDE ? n : BSTRIDE;
  }
  const int base = node * BSTRIDE;

  {
    int e = 2 * lane + j;
    if (valid && e < n) {
      int s = g_bsrc[base + e];
      float4 al = g_attl[s];
      float4 ar = g_attr[node];
      float v0 = al.x + ar.x, v1 = al.y + ar.y, v2 = al.z + ar.z, v3 = al.w + ar.w;
      v0 = v0 > 0.f ? v0 : 0.2f * v0; v1 = v1 > 0.f ? v1 : 0.2f * v1;
      v2 = v2 > 0.f ? v2 : 0.2f * v2; v3 = v3 > 0.f ? v3 : 0.2f * v3;
      s_src[wid][lane] = s;
      // permute to {u_h0, c_h0, u_h1, c_h1}
      s_ex[wid][lane] = make_float4(__expf(v0), __expf(v2), __expf(v1), __expf(v3));
    }
  }
  __syncwarp();

  const int hoff = (lane >= 16) ? 8 : 0;
  float4 accU = make_float4(0.f, 0.f, 0.f, 0.f);
  float4 accC = make_float4(0.f, 0.f, 0.f, 0.f);
  float denU = 0.f, denC = 0.f;

  const int nj = valid ? ((n - j + 1) >> 1) : 0;
  for (int i = 0; i < nj; i++) {
    int s = s_src[wid][i];
    float2 e01 = *(const float2*)((const char*)&s_ex[wid][i] + hoff);
    denU += e01.x; denC += e01.y;
    uint4 zz = *(const uint4*)&g_zh[s][lane * 8];   // {u01,u23,c01,c23}
    float2 u01 = __half22float2(*(const half2*)&zz.x);
    float2 u23 = __half22float2(*(const half2*)&zz.y);
    float2 c01 = __half22float2(*(const half2*)&zz.z);
    float2 c23 = __half22float2(*(const half2*)&zz.w);
    accU.x += e01.x * u01.x; accU.y += e01.x * u01.y;
    accU.z += e01.x * u23.x; accU.w += e01.x * u23.y;
    accC.x += e01.y * c01.x; accC.y += e01.y * c01.y;
    accC.z += e01.y * c23.x; accC.w += e01.y * c23.y;
  }

  if (j == 1) {
    s_pU[slot][lane] = accU;
    s_pC[slot][lane] = accC;
    if ((lane & 15) == 0) s_pd[slot][lane >> 4] = make_float2(denU, denC);
  }
  __syncthreads();
  if (j == 0 && valid) {
    float4 oU = s_pU[slot][lane];
    float4 oC = s_pC[slot][lane];
    float2 od = s_pd[slot][lane >> 4];
    accU.x += oU.x; accU.y += oU.y; accU.z += oU.z; accU.w += oU.w;
    accC.x += oC.x; accC.y += oC.y; accC.z += oC.z; accC.w += oC.w;
    denU += od.x; denC += od.y;

    float invU = denU > 0.f ? __frcp_rn(denU) : 0.f;
    float invC = denC > 0.f ? __frcp_rn(denC) : 0.f;
    const int cc = lane << 2;

    float4 cbu = *(const float4*)(cb + 128 + cc);
    float4 gbu = *(const float4*)(gb + 128 + cc);
    float4 cbc = *(const float4*)(cb + 256 + cc);
    float4 gbc = *(const float4*)(gb + 256 + cc);
    float4 hv  = *(const float4*)(h + (size_t)node * 128 + cc);

    float u0 = 1.f / (1.f + __expf(-(accU.x * invU + cbu.x + gbu.x)));
    float u1 = 1.f / (1.f + __expf(-(accU.y * invU + cbu.y + gbu.y)));
    float u2 = 1.f / (1.f + __expf(-(accU.z * invU + cbu.z + gbu.z)));
    float u3 = 1.f / (1.f + __expf(-(accU.w * invU + cbu.w + gbu.w)));
    float c0 = 1.f / (1.f + __expf(-(accC.x * invC + cbc.x + gbc.x)));
    float c1 = 1.f / (1.f + __expf(-(accC.y * invC + cbc.y + gbc.y)));
    float c2 = 1.f / (1.f + __expf(-(accC.z * invC + cbc.z + gbc.z)));
    float c3 = 1.f / (1.f + __expf(-(accC.w * invC + cbc.w + gbc.w)));

    float4 o;
    o.x = u0 * hv.x + (1.f - u0) * c0;
    o.y = u1 * hv.y + (1.f - u1) * c1;
    o.z = u2 * hv.z + (1.f - u2) * c2;
    o.w = u3 * hv.w + (1.f - u3) * c3;
    *(float4*)(out + (size_t)node * 128 + cc) = o;
  }
}

// ---------------------------------------------------------------------------
extern "C" void kernel_launch(void* const* d_in, const int* in_sizes, int n_in,
                              void* d_out, int out_size) {
  const float* x      = (const float*)d_in[0];
  const float* h      = (const float*)d_in[1];
  const float* W      = (const float*)d_in[2];
  const float* attn_l = (const float*)d_in[3];
  const float* attn_r = (const float*)d_in[4];
  const float* conv_b = (const float*)d_in[5];
  const float* gate_b = (const float*)d_in[6];
  const int*   src    = (const int*)d_in[7];
  const int*   dst    = (const int*)d_in[8];
  float* out = (float*)d_out;

  // One-time setup on the first (uncaptured correctness) call: smem attr +
  // side stream and fork/join events for intra-graph concurrency.
  static cudaStream_t s2 = nullptr;
  static cudaEvent_t evFork = nullptr, evJoin = nullptr;
  if (s2 == nullptr) {
    cudaFuncSetAttribute(k_gemm, cudaFuncAttributeMaxDynamicSharedMemorySize, SMT);
    cudaStreamCreateWithFlags(&s2, cudaStreamNonBlocking);
    cudaEventCreateWithFlags(&evFork, cudaEventDisableTiming);
    cudaEventCreateWithFlags(&evJoin, cudaEventDisableTiming);
  }

  k_prep<<<(NN + 255) / 256, 256>>>(W, attn_l, attn_r);

  // Fork: bucket + att (latency-bound, low occupancy) run on s2 concurrently
  // with the compute-bound gemm on the main stream.
  cudaEventRecord(evFork, 0);
  cudaStreamWaitEvent(s2, evFork, 0);

  dim3 ggrid((NN + 127) / 128, 2);
  k_gemm<<<ggrid, 256, SMT>>>(x);

  k_bucket<<<((NE / 4) + 255) / 256, 256, 0, s2>>>(src, dst);
  k_att<<<(NN * 32 + 255) / 256, 256, 0, s2>>>(x);

  // Join: agg needs z (gemm), buckets (bucket) and attention dots (att).
  cudaEventRecord(evJoin, s2);
  cudaStreamWaitEvent(0, evJoin, 0);

  k_agg<<<(NN + 1) / 2, 128>>>(h, conv_b, gate_b, out);
}